// round 11
// baseline (speedup 1.0000x reference)
#include <cuda_runtime.h>
#include <cuda_bf16.h>

// Problem constants (fixed by reference)
#define BN    4096
#define NTOTN 100000
#define DN    32
#define HN    64
#define TN    8
#define NEGV  (-1e9f)
#define EPB   4      // elements per block (1 warp each)

// Transposed stacked weights: WT4g[i4*64 + c] = (M[4i4][c],M[4i4+1][c],M[4i4+2][c],M[4i4+3][c])
// where M = [Wh (rows 0..63); Wk (rows 64..127)], c = output column.
__device__ float4 WT4g[32 * 64];

__global__ void gfn_prep_kernel(const float* __restrict__ Wh,
                                const float* __restrict__ Wk)
{
    int idx = blockIdx.x * blockDim.x + threadIdx.x;   // 0..2047
    if (idx >= 32 * 64) return;
    int i4 = idx >> 6, c = idx & 63;
    const float* M = (i4 < 16) ? Wh : Wk;
    int r0 = (i4 & 15) * 4;
    WT4g[idx] = make_float4(M[(r0 + 0) * HN + c], M[(r0 + 1) * HN + c],
                            M[(r0 + 2) * HN + c], M[(r0 + 3) * HN + c]);
}

// 128 threads = 4 warps = 4 elements, lockstepped per rollout step.
// Phase 1 (per live warp): keys gather + scores + fused LN + argmax/log-softmax.
// Phase 2 (whole block): batched hidden update; warp w computes output cols
// [16w,16w+16) for ALL 4 elements with broadcast-dense 128B W requests.
__global__ __launch_bounds__(128, 7)
void gfn_rollout_kernel(const float* __restrict__ qt,         // [B,64]
                        const int*   __restrict__ nbr,        // [NTOT,32]
                        const int*   __restrict__ start,      // [B]
                        const void*  __restrict__ evp,        // [NTOT,32] bool (dtype detected)
                        const float* __restrict__ keys,       // [NTOT,32,64]
                        const float* __restrict__ Wi,         // [64,64]
                        const float* __restrict__ g,          // [66]
                        const float* __restrict__ be,         // [66]
                        const float* __restrict__ sw,         // [66]
                        const float* __restrict__ sbp,        // [1]
                        const float* __restrict__ temp,       // [1]
                        float* __restrict__ out)
{
    // hidden/sel in i4-major layout: H4s[i4][e] = hidden_e[4i4..4i4+3]
    __shared__ __align__(16) float4 H4s[16][EPB];
    __shared__ __align__(16) float4 S4s[16][EPB];
    __shared__ int s_adv[EPB];

    float* Hf = (float*)H4s;

    const int tid   = threadIdx.x;
    const int w     = tid >> 5;      // warp id == element slot
    const int lane  = tid & 31;
    const int q     = lane & 15;
    const int hh    = lane >> 4;
    const int myrow = 2 * q + hh;
    const int b     = blockIdx.x * EPB + w;

    const float tclamp = fmaxf(temp[0], 1e-5f);
    const float itc    = 1.0f / tclamp;
    const float stop_b = sbp[0];

    // phase-2 lane mapping
    const int e2  = lane >> 3;       // element 0..3
    const int cg  = lane & 7;        // col group
    const int c0  = 16 * w + cg;
    const int c1  = c0 + 8;

    if (lane < 16) S4s[lane][w] = make_float4(0.f, 0.f, 0.f, 0.f);
    if (lane == 0) s_adv[w] = 0;

    // ---- detect edge_valid element width (word-typed int32/float32 vs byte bool) ----
    bool word_typed;
    {
        const unsigned* wv = (const unsigned*)evp;
        bool ok = true;
        #pragma unroll
        for (int i = 0; i < 4; i++) {
            unsigned v = wv[i * 32 + lane];
            ok &= (v == 0u || v == 1u || v == 0x3F800000u);
        }
        word_typed = __all_sync(0xffffffffu, ok);
    }
    const unsigned*      ev32 = (const unsigned*)evp;
    const unsigned char* ev8  = (const unsigned char*)evp;

    // ---- fold LN constants: ((c*rstd)*g+be)*sw == rstd*(Sg - mu*Gsum) + bsum ----
    const float gsw0 = __ldg(&g[lane])      * __ldg(&sw[lane]);
    const float gsw1 = __ldg(&g[lane + 32]) * __ldg(&sw[lane + 32]);
    float gsw64 = 0.f, gsw65 = 0.f;
    float bsum, Gsum;
    {
        float bs = __ldg(&be[lane]) * __ldg(&sw[lane])
                 + __ldg(&be[lane + 32]) * __ldg(&sw[lane + 32]);
        float gs = gsw0 + gsw1;
        if (lane == 0) {
            gsw64 = __ldg(&g[64]) * __ldg(&sw[64]);
            gsw65 = __ldg(&g[65]) * __ldg(&sw[65]);
            bs += __ldg(&be[64]) * __ldg(&sw[64]) + __ldg(&be[65]) * __ldg(&sw[65]);
            gs += gsw64 + gsw65;
        }
        #pragma unroll
        for (int o = 16; o; o >>= 1) {
            bs += __shfl_xor_sync(~0u, bs, o);
            gs += __shfl_xor_sync(~0u, gs, o);
        }
        bsum = bs; Gsum = gs;
    }

    // ---- init hidden = tanh(q[b] @ W_init) (per warp, Wi LDG, once) ----
    {
        Hf[(lane >> 2) * (4 * EPB) + w * 4 + (lane & 3)]        = qt[b * HN + lane];
        Hf[(8 + (lane >> 2)) * (4 * EPB) + w * 4 + (lane & 3)]  = qt[b * HN + lane + 32];
        __syncwarp();
        float4 acc = make_float4(0.f, 0.f, 0.f, 0.f);
        #pragma unroll
        for (int it = 0; it < 32; it++) {
            int i = 2 * it + hh;
            float hv = Hf[(i >> 2) * (4 * EPB) + w * 4 + (i & 3)];
            float4 wv = __ldg((const float4*)(Wi + i * HN + 4 * q));
            acc.x += hv * wv.x; acc.y += hv * wv.y;
            acc.z += hv * wv.z; acc.w += hv * wv.w;
        }
        acc.x += __shfl_xor_sync(0xffffffffu, acc.x, 16);
        acc.y += __shfl_xor_sync(0xffffffffu, acc.y, 16);
        acc.z += __shfl_xor_sync(0xffffffffu, acc.z, 16);
        acc.w += __shfl_xor_sync(0xffffffffu, acc.w, 16);
        __syncwarp();
        if (hh == 0) {
            H4s[q][w] = make_float4(tanhf(acc.x), tanhf(acc.y), tanhf(acc.z), tanhf(acc.w));
        }
        __syncwarp();
    }

    int   curr     = start[b];
    float lp_total = 0.f;
    int   nmoves   = 0;
    int   tstop    = TN;
    bool  live     = true;

    // output sections (float32, concatenated reference outputs)
    float* outA   = out;                          // actions_seq  [B,9]
    float* outTot = out + BN * 9;                 // log_pf_total [B]
    float* outS   = out + BN * 9 + BN;            // log_pf_steps [B,9]
    float* outNM  = out + BN * 9 + BN + BN * 9;   // num_moves    [B]

    for (int t = 0; t <= TN; t++) {
        if (live) {
            const float4* kb4 = (const float4*)(keys + (size_t)curr * (DN * HN));

            // early independent loads
            int nb = __ldg(&nbr[(size_t)curr * DN + myrow]);
            size_t evi = (size_t)curr * DN + myrow;
            int vraw = word_typed ? (ev32[evi] != 0u) : (ev8[evi] != 0);

            // fused gather + partial dots: p[it] = <keys[2it+hh], hidden>[chunk q]
            float4 h4 = H4s[q][w];
            float p[16];
            #pragma unroll
            for (int it = 0; it < 16; it++) {
                float4 v = __ldg(&kb4[it * 32 + lane]);
                p[it] = v.x * h4.x + v.y * h4.y + v.z * h4.z + v.w * h4.w;
            }
            // transpose-reduce: lane (q,hh) ends with score of row 2q+hh
            #pragma unroll
            for (int k = 8; k >= 1; k >>= 1) {
                bool hi = (q & k) != 0;
                #pragma unroll
                for (int i = 0; i < 8; i++) {
                    if (i < k) {
                        float send = hi ? p[i] : p[i + k];
                        float recv = __shfl_xor_sync(0xffffffffu, send, k);
                        p[i] = (hi ? p[i + k] : p[i]) + recv;
                    }
                }
            }
            float sc = p[0];

            int vd = (t < TN) ? vraw : 0;
            unsigned vm = __ballot_sync(0xffffffffu, vd);
            float has_edge = vm ? 1.f : 0.f;
            float logit = (vd ? sc : NEGV) * itc;

            // fused single-pass LN (S1, S2, Sg reduced together)
            float x0 = Hf[(lane >> 2) * (4 * EPB) + w * 4 + (lane & 3)];
            float x1 = Hf[(8 + (lane >> 2)) * (4 * EPB) + w * 4 + (lane & 3)];
            float e64 = (float)t / (float)TN;
            float e65 = has_edge;
            float s1 = x0 + x1;
            float s2 = x0 * x0 + x1 * x1;
            float sg = x0 * gsw0 + x1 * gsw1;
            if (lane == 0) {
                s1 += e64 + e65;
                s2 += e64 * e64 + e65 * e65;
                sg += e64 * gsw64 + e65 * gsw65;
            }
            #pragma unroll
            for (int o = 16; o; o >>= 1) {
                s1 += __shfl_xor_sync(~0u, s1, o);
                s2 += __shfl_xor_sync(~0u, s2, o);
                sg += __shfl_xor_sync(~0u, sg, o);
            }
            float mu = s1 * (1.f / 66.f);
            float var = s2 * (1.f / 66.f) - mu * mu;
            float rstd = rsqrtf(var + 1e-5f);
            float stop_logit = ((sg - mu * Gsum) * rstd + bsum + stop_b) * itc;

            // argmax (first-max by row id), then stop (strict >)
            float bv = logit; int bi = myrow;
            #pragma unroll
            for (int o = 16; o; o >>= 1) {
                float ov = __shfl_xor_sync(~0u, bv, o);
                int   oi = __shfl_xor_sync(~0u, bi, o);
                if (ov > bv || (ov == bv && oi < bi)) { bv = ov; bi = oi; }
            }
            int action; float chosen;
            if (stop_logit > bv) { action = DN; chosen = stop_logit; }
            else                 { action = bi; chosen = bv; }

            // log-softmax denominator over 33
            float m = fmaxf(bv, stop_logit);
            float es = expf(logit - m);
            #pragma unroll
            for (int o = 16; o; o >>= 1) es += __shfl_xor_sync(~0u, es, o);
            es += expf(stop_logit - m);
            float lp = chosen - (m + logf(es));

            bool chose_stop = (action == DN);
            int  a = chose_stop ? (DN - 1) : action;
            int  act_rec = chose_stop ? -1 : curr * DN + a;

            if (lane == 0) {
                outA[b * 9 + t] = (float)act_rec;
                outS[b * 9 + t] = lp;
            }
            lp_total += lp;

            if (chose_stop) {
                live  = false;
                tstop = t;
                if (lane == 0) s_adv[w] = 0;
            } else {
                nmoves++;
                int src_lane = (a >> 1) | ((a & 1) << 4);
                int tail = __shfl_sync(0xffffffffu, nb, src_lane);
                if (lane < 16) S4s[lane][w] = __ldg(&kb4[a * 16 + lane]);
                if (lane == 0) s_adv[w] = 1;
                curr = tail;
            }
        }

        int nlive = __syncthreads_count((int)live);   // barrier 1 (s_adv/S4s visible)
        if (nlive == 0) break;

        // ---- phase 2: batched hidden update, broadcast-dense W requests ----
        int anyadv = s_adv[0] | s_adv[1] | s_adv[2] | s_adv[3];
        float acc0 = 0.f, acc1 = 0.f;
        if (anyadv) {
            float a0a = 0.f, a0b = 0.f, a1a = 0.f, a1b = 0.f;
            #pragma unroll
            for (int i4 = 0; i4 < 16; i4++) {
                float4 hv = H4s[i4][e2];
                float4 w0 = __ldg(&WT4g[i4 * 64 + c0]);
                float4 w1 = __ldg(&WT4g[i4 * 64 + c1]);
                a0a += hv.x * w0.x + hv.y * w0.y;
                a0b += hv.z * w0.z + hv.w * w0.w;
                a1a += hv.x * w1.x + hv.y * w1.y;
                a1b += hv.z * w1.z + hv.w * w1.w;
            }
            #pragma unroll
            for (int i4 = 0; i4 < 16; i4++) {
                float4 sv = S4s[i4][e2];
                float4 w0 = __ldg(&WT4g[(16 + i4) * 64 + c0]);
                float4 w1 = __ldg(&WT4g[(16 + i4) * 64 + c1]);
                a0a += sv.x * w0.x + sv.y * w0.y;
                a0b += sv.z * w0.z + sv.w * w0.w;
                a1a += sv.x * w1.x + sv.y * w1.y;
                a1b += sv.z * w1.z + sv.w * w1.w;
            }
            acc0 = a0a + a0b;
            acc1 = a1a + a1b;
        }
        int adv = s_adv[e2];
        __syncthreads();                              // barrier 2: all reads of H/S done
        if (anyadv && adv) {
            Hf[(c0 >> 2) * (4 * EPB) + e2 * 4 + (c0 & 3)] = tanhf(acc0);
            Hf[(c1 >> 2) * (4 * EPB) + e2 * 4 + (c1 & 3)] = tanhf(acc1);
        }
        __syncthreads();                              // barrier 3: writeback visible
    }

    // ---- fill forced-stopped tail steps + totals ----
    if (lane == 0) {
        for (int tt = tstop + 1; tt <= TN; tt++) {
            outA[b * 9 + tt] = -1.f;
            outS[b * 9 + tt] = 0.f;
        }
        outTot[b] = lp_total;
        outNM[b]  = (float)nmoves;
    }
}

extern "C" void kernel_launch(void* const* d_in, const int* in_sizes, int n_in,
                              void* d_out, int out_size)
{
    const float* q     = (const float*)d_in[0];
    const int*   nbr   = (const int*)d_in[1];
    const int*   start = (const int*)d_in[2];
    const void*  ev    = (const void*)d_in[3];
    const float* keys  = (const float*)d_in[4];
    const float* Wi    = (const float*)d_in[5];
    const float* Wh    = (const float*)d_in[6];
    const float* Wk    = (const float*)d_in[7];
    const float* g     = (const float*)d_in[8];
    const float* be    = (const float*)d_in[9];
    const float* sw    = (const float*)d_in[10];
    const float* sb    = (const float*)d_in[11];
    const float* temp  = (const float*)d_in[12];
    float* out = (float*)d_out;

    gfn_prep_kernel<<<8, 256>>>(Wh, Wk);
    gfn_rollout_kernel<<<BN / EPB, 128>>>(q, nbr, start, ev, keys, Wi,
                                          g, be, sw, sb, temp, out);
}